// round 13
// baseline (speedup 1.0000x reference)
#include <cuda_runtime.h>
#include <stdint.h>

// Problem shape (fixed by the dataset)
constexpr int B       = 4;
constexpr int N       = 32768;
constexpr int NQ      = 2048;
constexpr int K       = 16;
constexpr int QSTRIDE = N / NQ;   // 16

constexpr int TILE    = 1024;          // candidate points per smem tile
constexpr int PAIRS   = TILE / 2;
constexpr int WPB     = 4;             // warps per block
constexpr int QPW     = 4;             // queries per warp (2 packed f32x2 pairs)
constexpr int THREADS = WPB * 32;      // 128
constexpr int QPB     = WPB * QPW;     // 16 queries per block
constexpr int BLOCKS_PER_BATCH = NQ / QPB;  // 128

typedef unsigned long long u64;
typedef unsigned int u32;

constexpr u64 KEY_INF = ~0ULL;
constexpr u32 FULL    = 0xffffffffu;

// ---- packed 2xfp32 helpers (Blackwell f32x2; .rn per half == scalar rn) ----
__device__ __forceinline__ u64 add2(u64 a, u64 b) {
    u64 r; asm("add.rn.f32x2 %0, %1, %2;" : "=l"(r) : "l"(a), "l"(b)); return r;
}
__device__ __forceinline__ u64 mul2(u64 a, u64 b) {
    u64 r; asm("mul.rn.f32x2 %0, %1, %2;" : "=l"(r) : "l"(a), "l"(b)); return r;
}
// fma(p, -1, q) = rn(q - p) exactly (p*-1 is exact, single rounding on add).
__device__ __forceinline__ u64 fma2(u64 a, u64 b, u64 c) {
    u64 r; asm("fma.rn.f32x2 %0, %1, %2, %3;" : "=l"(r) : "l"(a), "l"(b), "l"(c)); return r;
}
__device__ __forceinline__ u64 pk(u32 lo, u32 hi) {
    u64 r; asm("mov.b64 %0, {%1, %2};" : "=l"(r) : "r"(lo), "r"(hi)); return r;
}
__device__ __forceinline__ void unpk(u32& lo, u32& hi, u64 v) {
    asm("mov.b64 {%0, %1}, %2;" : "=r"(lo), "=r"(hi) : "l"(v));
}

// Insert up to 32 candidate keys (nk, invalid lanes = KEY_INF, mask m) into
// the warp-distributed sorted list L (lane i holds element i, ascending).
__device__ __forceinline__ void warp_insert(u64& L, u64 nk, u32 m, int lane) {
    if (__popc(m) <= 2) {
        while (m) {                       // 1-2 keys: distributed shift-insert
            const int src = __ffs(m) - 1;
            m &= m - 1;
            const u64 k  = __shfl_sync(FULL, nk, src);
            const u64 up = __shfl_up_sync(FULL, L, 1);
            if (k < L) L = (lane > 0 && k < up) ? up : k;
        }
    } else {
        // Bitonic sort 32 candidates ascending.
#pragma unroll
        for (int k2 = 2; k2 <= 32; k2 <<= 1) {
#pragma unroll
            for (int j2 = k2 >> 1; j2 >= 1; j2 >>= 1) {
                const u64 o = __shfl_xor_sync(FULL, nk, j2);
                const bool takemin = ((lane & j2) == 0) == ((lane & k2) == 0);
                const bool pl = nk < o;
                nk = (pl == takemin) ? nk : o;
            }
        }
        // Old (asc) vs new reversed (desc): min keeps 32 smallest (bitonic),
        // then clean-up merge.
        const u64 r = __shfl_sync(FULL, nk, 31 - lane);
        L = (L < r) ? L : r;
#pragma unroll
        for (int j2 = 16; j2 >= 1; j2 >>= 1) {
            const u64 o = __shfl_xor_sync(FULL, L, j2);
            const bool takemin = ((lane & j2) == 0);
            const bool pl = L < o;
            L = (pl == takemin) ? L : o;
        }
    }
}

// Exact sub-insert: u64 key (hi = distance bits, lo = idx), exact
// lexicographic test vs CURRENT threshold, merge, refresh threshold.
__device__ __forceinline__ void try_insert(u64& L, u64& T, u32& Thi,
                                           u32 dbits, int cidx, int lane) {
    const u64 ck = pk((u32)cidx, dbits);
    const bool v = ck < T;
    const u32 m = __ballot_sync(FULL, v);
    if (m) {
        warp_insert(L, v ? ck : KEY_INF, m, lane);
        T   = __shfl_sync(FULL, L, K - 1);
        Thi = (u32)(T >> 32);
    }
}

// One warp handles FOUR queries as two f32x2 pairs. Each lane processes 2
// candidates per step from a duplicated smem layout (3 x LDS.128 per 2
// candidates), so LDS bytes and loop overhead are amortized over 4 queries.
// Distances are bit-exact fp32 (fma(p,-1,q) diff, ((dx^2+dy^2)+dz^2), rn),
// so u64 key order == jax.lax.top_k's (d asc, idx asc).
__global__ __launch_bounds__(THREADS, 4)
void knn_kernel(const float* __restrict__ xyz, float* __restrict__ out) {
    // Per pair i (candidates 2i, 2i+1): sX[i] = {(x0,x0),(x1,x1)}, etc.
    __shared__ ulonglong2 sX[PAIRS], sY[PAIRS], sZ[PAIRS];

    const int lane  = threadIdx.x & 31;
    const int warp  = threadIdx.x >> 5;
    const int batch = blockIdx.x >> 7;                      // / BLOCKS_PER_BATCH
    const int q0    = (blockIdx.x & (BLOCKS_PER_BATCH - 1)) * QPB + warp * QPW;

    const float* __restrict__ base = xyz + (size_t)batch * N * 3;

    float qx[QPW], qy[QPW], qz[QPW];
#pragma unroll
    for (int r = 0; r < QPW; ++r) {
        qx[r] = base[(q0 + r) * QSTRIDE * 3 + 0];
        qy[r] = base[(q0 + r) * QSTRIDE * 3 + 1];
        qz[r] = base[(q0 + r) * QSTRIDE * 3 + 2];
    }
    // Packed query pairs: P0 = (q0,q1), P1 = (q2,q3)
    const u64 qxP0 = pk(__float_as_uint(qx[0]), __float_as_uint(qx[1]));
    const u64 qyP0 = pk(__float_as_uint(qy[0]), __float_as_uint(qy[1]));
    const u64 qzP0 = pk(__float_as_uint(qz[0]), __float_as_uint(qz[1]));
    const u64 qxP1 = pk(__float_as_uint(qx[2]), __float_as_uint(qx[3]));
    const u64 qyP1 = pk(__float_as_uint(qy[2]), __float_as_uint(qy[3]));
    const u64 qzP1 = pk(__float_as_uint(qz[2]), __float_as_uint(qz[3]));

    const u32 n1 = 0xBF800000u;                 // -1.0f bits
    const u64 NEG1 = pk(n1, n1);

    u64 L0 = KEY_INF, L1 = KEY_INF, L2 = KEY_INF, L3 = KEY_INF;
    u64 T0 = KEY_INF, T1 = KEY_INF, T2 = KEY_INF, T3 = KEY_INF;
    u32 T0h = FULL, T1h = FULL, T2h = FULL, T3h = FULL;

    for (int t = 0; t < N; t += TILE) {
        __syncthreads();
        for (int i = threadIdx.x; i < PAIRS; i += THREADS) {
            const float* __restrict__ p = base + (size_t)(t + 2 * i) * 3;
            const u32 x0 = __float_as_uint(p[0]), y0 = __float_as_uint(p[1]);
            const u32 z0 = __float_as_uint(p[2]), x1 = __float_as_uint(p[3]);
            const u32 y1 = __float_as_uint(p[4]), z1 = __float_as_uint(p[5]);
            sX[i] = make_ulonglong2(pk(x0, x0), pk(x1, x1));
            sY[i] = make_ulonglong2(pk(y0, y0), pk(y1, y1));
            sZ[i] = make_ulonglong2(pk(z0, z0), pk(z1, z1));
        }
        __syncthreads();

#pragma unroll 4
        for (int s = 0; s < PAIRS / 32; ++s) {
            const int i = s * 32 + lane;
            const ulonglong2 px = sX[i];   // (x_a,x_a) (x_b,x_b)
            const ulonglong2 py = sY[i];
            const ulonglong2 pz = sZ[i];

            // Candidate a vs pair P0 / P1
            const u64 dxa0 = fma2(px.x, NEG1, qxP0);
            const u64 dya0 = fma2(py.x, NEG1, qyP0);
            const u64 dza0 = fma2(pz.x, NEG1, qzP0);
            const u64 daP0 = add2(add2(mul2(dxa0, dxa0), mul2(dya0, dya0)),
                                  mul2(dza0, dza0));
            const u64 dxa1 = fma2(px.x, NEG1, qxP1);
            const u64 dya1 = fma2(py.x, NEG1, qyP1);
            const u64 dza1 = fma2(pz.x, NEG1, qzP1);
            const u64 daP1 = add2(add2(mul2(dxa1, dxa1), mul2(dya1, dya1)),
                                  mul2(dza1, dza1));
            // Candidate b
            const u64 dxb0 = fma2(px.y, NEG1, qxP0);
            const u64 dyb0 = fma2(py.y, NEG1, qyP0);
            const u64 dzb0 = fma2(pz.y, NEG1, qzP0);
            const u64 dbP0 = add2(add2(mul2(dxb0, dxb0), mul2(dyb0, dyb0)),
                                  mul2(dzb0, dzb0));
            const u64 dxb1 = fma2(px.y, NEG1, qxP1);
            const u64 dyb1 = fma2(py.y, NEG1, qyP1);
            const u64 dzb1 = fma2(pz.y, NEG1, qzP1);
            const u64 dbP1 = add2(add2(mul2(dxb1, dxb1), mul2(dyb1, dyb1)),
                                  mul2(dzb1, dzb1));

            u32 d0a, d1a, d2a, d3a, d0b, d1b, d2b, d3b;
            unpk(d0a, d1a, daP0);
            unpk(d2a, d3a, daP1);
            unpk(d0b, d1b, dbP0);
            unpk(d2b, d3b, dbP1);

            // d >= 0 always, so float order == unsigned bit order.
            const bool trig = (d0a <= T0h) | (d1a <= T1h) |
                              (d2a <= T2h) | (d3a <= T3h) |
                              (d0b <= T0h) | (d1b <= T1h) |
                              (d2b <= T2h) | (d3b <= T3h);
            if (__any_sync(FULL, trig)) {
                const int ca = t + 2 * i;
                try_insert(L0, T0, T0h, d0a, ca,     lane);
                try_insert(L0, T0, T0h, d0b, ca + 1, lane);
                try_insert(L1, T1, T1h, d1a, ca,     lane);
                try_insert(L1, T1, T1h, d1b, ca + 1, lane);
                try_insert(L2, T2, T2h, d2a, ca,     lane);
                try_insert(L2, T2, T2h, d2b, ca + 1, lane);
                try_insert(L3, T3, T3h, d3a, ca,     lane);
                try_insert(L3, T3, T3h, d3b, ca + 1, lane);
            }
        }
    }

    // Output 0: idx (B, NQ, K, 1) as fp32 (values < 2^15, exact).
    // Output 1: pts (B, NQ, 3) fp32.
    float* __restrict__ out_idx = out;
    float* __restrict__ out_pts = out + (size_t)B * NQ * K;

    const int qg0 = batch * NQ + q0;
    if (lane < K) {
        out_idx[(size_t)(qg0 + 0) * K + lane] = (float)(u32)(L0 & 0xffffffffu);
        out_idx[(size_t)(qg0 + 1) * K + lane] = (float)(u32)(L1 & 0xffffffffu);
        out_idx[(size_t)(qg0 + 2) * K + lane] = (float)(u32)(L2 & 0xffffffffu);
        out_idx[(size_t)(qg0 + 3) * K + lane] = (float)(u32)(L3 & 0xffffffffu);
    }
    if (lane == 0) {
#pragma unroll
        for (int r = 0; r < QPW; ++r) {
            out_pts[(size_t)(qg0 + r) * 3 + 0] = qx[r];
            out_pts[(size_t)(qg0 + r) * 3 + 1] = qy[r];
            out_pts[(size_t)(qg0 + r) * 3 + 2] = qz[r];
        }
    }
}

extern "C" void kernel_launch(void* const* d_in, const int* in_sizes, int n_in,
                              void* d_out, int out_size) {
    (void)in_sizes; (void)n_in; (void)out_size;
    const float* xyz = (const float*)d_in[0];
    float* out = (float*)d_out;

    const int grid = B * BLOCKS_PER_BATCH;   // 512 blocks
    knn_kernel<<<grid, THREADS>>>(xyz, out);
}

// round 14
// speedup vs baseline: 1.2159x; 1.2159x over previous
#include <cuda_runtime.h>
#include <stdint.h>

typedef unsigned long long u64;
typedef unsigned int u32;

// Problem shape (fixed by the dataset)
constexpr int B       = 4;
constexpr int N       = 32768;
constexpr int NQ      = 2048;
constexpr int K       = 16;
constexpr int QSTRIDE = N / NQ;   // 16

// Spatial grid: h = 0.25 (power of two -> exact cell boundaries), covering
// [-5, 5)^3; coordinates outside are clamped into edge cells (their stored
// coords stay exact, so distances and the pruning bound remain valid).
constexpr int   G    = 40;
constexpr int   NC   = G * G * G;       // 64000 cells
constexpr float XMIN = -5.0f;
constexpr float H    = 0.25f;
constexpr float INVH = 4.0f;

constexpr u64 KEY_INF = ~0ULL;
constexpr u32 FULL    = 0xffffffffu;

// Device scratch (static allocation -- no cudaMalloc anywhere)
__device__ float4 g_pts[B][N];          // cell-sorted points, w = idx bits
__device__ u32    g_count[B][NC];
__device__ u32    g_start[B][NC + 1];
__device__ u32    g_cursor[B][NC];

__device__ __forceinline__ int cellof(float v) {
    int c = (int)floorf((v - XMIN) * INVH);
    return min(max(c, 0), G - 1);
}

__device__ __forceinline__ u64 pk(u32 lo, u32 hi) {
    u64 r; asm("mov.b64 %0, {%1, %2};" : "=l"(r) : "r"(lo), "r"(hi)); return r;
}

// ---------------- build kernels ----------------

__global__ void zero_kernel() {
    int i = blockIdx.x * blockDim.x + threadIdx.x;
    if (i < B * NC) ((u32*)g_count)[i] = 0;
}

__global__ void hist_kernel(const float* __restrict__ xyz) {
    int i = blockIdx.x * blockDim.x + threadIdx.x;
    if (i >= B * N) return;
    int b = i >> 15, p = i & (N - 1);
    const float* q = xyz + (size_t)b * N * 3 + (size_t)p * 3;
    int c = (cellof(q[2]) * G + cellof(q[1])) * G + cellof(q[0]);
    atomicAdd(&g_count[b][c], 1u);
}

__global__ void scan_kernel() {
    const int b = blockIdx.x;
    const int t = threadIdx.x;
    const int IT = (NC + 1023) / 1024;      // 63
    const int s0 = t * IT;
    const int s1 = min(s0 + IT, NC);

    u32 sum = 0;
    for (int i = s0; i < s1; ++i) sum += g_count[b][i];

    __shared__ u32 sh[1024];
    sh[t] = sum;
    __syncthreads();
    for (int off = 1; off < 1024; off <<= 1) {
        u32 v = 0;
        if (t >= off) v = sh[t - off];
        __syncthreads();
        if (t >= off) sh[t] += v;
        __syncthreads();
    }
    u32 prefix = (t > 0) ? sh[t - 1] : 0;    // exclusive prefix of my chunk
    for (int i = s0; i < s1; ++i) {
        g_start[b][i]  = prefix;
        g_cursor[b][i] = prefix;
        prefix += g_count[b][i];
    }
    if (t == 0) g_start[b][NC] = sh[1023];
}

__global__ void scatter_kernel(const float* __restrict__ xyz) {
    int i = blockIdx.x * blockDim.x + threadIdx.x;
    if (i >= B * N) return;
    int b = i >> 15, p = i & (N - 1);
    const float* q = xyz + (size_t)b * N * 3 + (size_t)p * 3;
    float x = q[0], y = q[1], z = q[2];
    int c = (cellof(z) * G + cellof(y)) * G + cellof(x);
    u32 pos = atomicAdd(&g_cursor[b][c], 1u);
    g_pts[b][pos] = make_float4(x, y, z, __uint_as_float((u32)p));
}

// ---------------- exact top-K machinery (proven in prior rounds) ----------

// Insert up to 32 candidate keys (nk; invalid lanes = KEY_INF, mask m) into
// the warp-distributed sorted list L (lane i holds element i, ascending).
__device__ __forceinline__ void warp_insert(u64& L, u64 nk, u32 m, int lane) {
    if (__popc(m) <= 2) {
        while (m) {                        // 1-2 keys: distributed shift-insert
            const int src = __ffs(m) - 1;
            m &= m - 1;
            const u64 k  = __shfl_sync(FULL, nk, src);
            const u64 up = __shfl_up_sync(FULL, L, 1);
            if (k < L) L = (lane > 0 && k < up) ? up : k;
        }
    } else {
        // Bitonic sort 32 candidates ascending.
#pragma unroll
        for (int k2 = 2; k2 <= 32; k2 <<= 1) {
#pragma unroll
            for (int j2 = k2 >> 1; j2 >= 1; j2 >>= 1) {
                const u64 o = __shfl_xor_sync(FULL, nk, j2);
                const bool takemin = ((lane & j2) == 0) == ((lane & k2) == 0);
                const bool pl = nk < o;
                nk = (pl == takemin) ? nk : o;
            }
        }
        // Old (asc) vs new reversed (desc): min -> bitonic of 32 smallest.
        const u64 r = __shfl_sync(FULL, nk, 31 - lane);
        L = (L < r) ? L : r;
#pragma unroll
        for (int j2 = 16; j2 >= 1; j2 >>= 1) {
            const u64 o = __shfl_xor_sync(FULL, L, j2);
            const bool takemin = ((lane & j2) == 0);
            const bool pl = L < o;
            L = (pl == takemin) ? L : o;
        }
    }
}

// Scan a contiguous run [s, e) of cell-sorted points against one query.
// Distances bit-exact fp32 (rn subs/muls/adds, ((dx^2+dy^2)+dz^2)); key
// order == jax.lax.top_k's (d asc, idx asc).
__device__ __forceinline__ void scan_span(const float4* __restrict__ pts,
                                          u32 s, u32 e,
                                          float qx, float qy, float qz,
                                          int lane, u64& L, u64& T, u32& Th) {
    for (u32 i = s + lane; __any_sync(FULL, i < e); i += 32) {
        const bool act = i < e;
        u32 dbits = FULL, pidx = 0;
        if (act) {
            const float4 p = pts[i];
            const float dx = __fsub_rn(qx, p.x);
            const float dy = __fsub_rn(qy, p.y);
            const float dz = __fsub_rn(qz, p.z);
            const float d  = __fadd_rn(__fadd_rn(__fmul_rn(dx, dx),
                                                 __fmul_rn(dy, dy)),
                                       __fmul_rn(dz, dz));
            dbits = __float_as_uint(d);
            pidx  = __float_as_uint(p.w);
        }
        const u64 ck = pk(pidx, dbits);
        const bool v = act && (ck < T);        // exact lexicographic test
        const u32 m = __ballot_sync(FULL, v);
        if (m) {
            warp_insert(L, v ? ck : KEY_INF, m, lane);
            T  = __shfl_sync(FULL, L, K - 1);
            Th = (u32)(T >> 32);
        }
    }
}

// ---------------- query kernel ----------------

constexpr int QWARPS_PER_BLOCK = 8;
constexpr int QTHREADS = QWARPS_PER_BLOCK * 32;   // 256

__global__ __launch_bounds__(QTHREADS)
void query_kernel(const float* __restrict__ xyz, float* __restrict__ out) {
    const int lane = threadIdx.x & 31;
    const int warp = threadIdx.x >> 5;
    const int qg   = blockIdx.x * QWARPS_PER_BLOCK + warp;
    const int b    = qg >> 11;                    // / NQ
    const int q    = qg & (NQ - 1);

    const float* __restrict__ base = xyz + (size_t)b * N * 3;
    const int qidx = q * QSTRIDE;
    const float qx = base[qidx * 3 + 0];
    const float qy = base[qidx * 3 + 1];
    const float qz = base[qidx * 3 + 2];

    const int cx = cellof(qx), cy = cellof(qy), cz = cellof(qz);

    const float4* __restrict__ pts = g_pts[b];
    const u32*    __restrict__ st  = g_start[b];

    u64 L = KEY_INF, T = KEY_INF;
    u32 Th = FULL;

    // Scan one x-contiguous row of cells [x0, x1] at (zz, yy).
    auto row = [&](int zz, int yy, int x0, int x1) {
        x0 = max(x0, 0);
        x1 = min(x1, G - 1);
        if (x0 > x1) return;
        const int rb = (zz * G + yy) * G;
        const u32 s = st[rb + x0];
        const u32 e = st[rb + x1 + 1];
        if (s < e) scan_span(pts, s, e, qx, qy, qz, lane, L, T, Th);
    };

    // Phase A: full box of Chebyshev radius 1 (27 cells, 9 rows).
    for (int dz = -1; dz <= 1; ++dz) {
        const int zz = cz + dz;
        if (zz < 0 || zz >= G) continue;
        for (int dy = -1; dy <= 1; ++dy) {
            const int yy = cy + dy;
            if (yy < 0 || yy >= G) continue;
            row(zz, yy, cx - 1, cx + 1);
        }
    }

    // Phase B: expand rings while unscanned cells could hold a better key.
    for (int r = 1; r < G; ++r) {
        // Conservative lower bound on the distance from q to any point in a
        // cell OUTSIDE the box of radius r. Cell boundaries XMIN + k*H are
        // exact fp32; round-down subs/mul give a true lower bound; the 1e-5
        // margin covers boundary-assignment rounding fuzz (~1e-6).
        const float lox = XMIN + (float)(cx - r) * H;
        const float hix = XMIN + (float)(cx + r + 1) * H;
        const float loy = XMIN + (float)(cy - r) * H;
        const float hiy = XMIN + (float)(cy + r + 1) * H;
        const float loz = XMIN + (float)(cz - r) * H;
        const float hiz = XMIN + (float)(cz + r + 1) * H;
        float m = fminf(__fsub_rd(qx, lox), __fsub_rd(hix, qx));
        m = fminf(m, fminf(__fsub_rd(qy, loy), __fsub_rd(hiy, qy)));
        m = fminf(m, fminf(__fsub_rd(qz, loz), __fsub_rd(hiz, qz)));
        m = __fsub_rd(m, 1e-5f);
        if (m > 0.0f) {
            const float b2 = __fmul_rd(m, m);
            // Strict >: equal-distance unscanned points (which could win a
            // tie on index) keep the scan going. Unsigned bit compare is
            // exact for non-negative floats; Th == 0xFFFFFFFF (unfilled
            // sentinel) can never satisfy it.
            if (__float_as_uint(b2) > Th) break;
        }
        // Scan ring r+1 (cells at Chebyshev distance exactly r+1).
        const int rr = r + 1;
        for (int dz = -rr; dz <= rr; ++dz) {
            const int zz = cz + dz;
            if (zz < 0 || zz >= G) continue;
            const bool zedge = (dz == -rr) || (dz == rr);
            for (int dy = -rr; dy <= rr; ++dy) {
                const int yy = cy + dy;
                if (yy < 0 || yy >= G) continue;
                if (zedge || dy == -rr || dy == rr) {
                    row(zz, yy, cx - rr, cx + rr);        // full row
                } else {
                    row(zz, yy, cx - rr, cx - rr);        // two x-end cells
                    row(zz, yy, cx + rr, cx + rr);
                }
            }
        }
    }

    // Output 0: idx (B, NQ, K, 1) as fp32 (values < 2^15, exact).
    // Output 1: pts (B, NQ, 3) fp32.
    float* __restrict__ out_idx = out;
    float* __restrict__ out_pts = out + (size_t)B * NQ * K;

    if (lane < K)
        out_idx[(size_t)qg * K + lane] = (float)(u32)(L & 0xffffffffu);
    if (lane == 0) {
        out_pts[(size_t)qg * 3 + 0] = qx;
        out_pts[(size_t)qg * 3 + 1] = qy;
        out_pts[(size_t)qg * 3 + 2] = qz;
    }
}

// ---------------- launch ----------------

extern "C" void kernel_launch(void* const* d_in, const int* in_sizes, int n_in,
                              void* d_out, int out_size) {
    (void)in_sizes; (void)n_in; (void)out_size;
    const float* xyz = (const float*)d_in[0];
    float* out = (float*)d_out;

    zero_kernel<<<(B * NC + 255) / 256, 256>>>();
    hist_kernel<<<(B * N + 255) / 256, 256>>>(xyz);
    scan_kernel<<<B, 1024>>>();
    scatter_kernel<<<(B * N + 255) / 256, 256>>>(xyz);
    query_kernel<<<(B * NQ) / QWARPS_PER_BLOCK, QTHREADS>>>(xyz, out);
}